// round 16
// baseline (speedup 1.0000x reference)
#include <cuda_runtime.h>
#include <cuda_bf16.h>

// HXELoss: B=256 rows, C=4096 classes, 8-ary tree depth 4.
// per_sample(b) = sum_j w[t,j]*(log E_{8^(j+1)} - log E_{8^j}); Z & max cancel.
//
// R15 finding: the fused-kernel floor (~7.1us vs 3.8us for the bare wave) was
// 256 simultaneous single-address atomics serializing at the L2 atomic ALU
// (~27 cyc/op = ~3.4us). Fix: HIERARCHICAL ticket -- 16 group counters spaced
// 256B apart (distinct LTS slices), 16 arrivals each in parallel (~430 cyc),
// group-lasts hit one root counter (16 ops, ~430 cyc). ~900 cyc total.
// acq_rel chain gives transitive visibility of all 256 partials to the final
// reducer. Fixed-order sum -> deterministic. All counters wrap -> replay-safe.
//
// 256 CTAs x 256 thr, 1 row/CTA, single wave, float4 loads, plain f32 __expf
// (MUFU throughput is 16 exp/cyc/SM -- never the bottleneck).
// Targets are int32 on device (JAX x64 disabled downcasts int64).

#define Bn   256
#define Cn   4096
#define TPB  256
#define VPT  4            // float4s per thread (256 thr * 4 * 4 = 4096 floats)
#define NGRP 16
#define CSTRIDE 64        // 64 u32 = 256 bytes between counters

__device__ float        g_partial[Bn];
__device__ unsigned int g_cnt[NGRP * CSTRIDE];   // zero-init; wraps keep it 0
__device__ unsigned int g_root = 0;

__device__ __forceinline__ float warpSum(float x) {
#pragma unroll
    for (int o = 16; o > 0; o >>= 1) x += __shfl_xor_sync(0xffffffffu, x, o);
    return x;
}

__global__ __launch_bounds__(TPB) void hxe_fused(
    const float* __restrict__ logits,
    const int* __restrict__ tgt,
    const float* __restrict__ weights,
    float* __restrict__ out)
{
    const int b   = blockIdx.x;
    const int tid = threadIdx.x;
    const int wid = tid >> 5;
    const int lid = tid & 31;

    const float4* row4 = (const float4*)(logits + (size_t)b * Cn);

    // ---- target & block ids (int32 storage!) ----
    const int t  = tgt[b * 4 + 3];
    const int t2 = t >> 2;
    const int t3 = t >> 3;
    const int t6 = t >> 6;
    const int t9 = t >> 9;
    const int tk = t & 3;

    // ---- load row (float4, coalesced, front-batched: MLP=4) ----
    float4 v[VPT];
#pragma unroll
    for (int i = 0; i < VPT; i++) v[i] = row4[tid + i * TPB];

    // ---- nested exp-block sums; group-of-4 shares block predicates ----
    float et = 0.f, e8 = 0.f, e64 = 0.f, e512 = 0.f, Z = 0.f;
#pragma unroll
    for (int i = 0; i < VPT; i++) {
        const int g = tid + i * TPB;         // classes 4g..4g+3
        const float e0 = __expf(v[i].x);
        const float e1 = __expf(v[i].y);
        const float e2 = __expf(v[i].z);
        const float e3 = __expf(v[i].w);
        const float s4 = (e0 + e1) + (e2 + e3);
        Z += s4;
        const int c = g << 2;
        if ((c >> 9) == t9) {
            e512 += s4;
            if ((c >> 6) == t6) {
                e64 += s4;
                if ((c >> 3) == t3) {
                    e8 += s4;
                    if (g == t2) et = (tk == 0) ? e0 : (tk == 1) ? e1 : (tk == 2) ? e2 : e3;
                }
            }
        }
    }

    // ---- block reduce the 5 partials (8 warps) ----
    __shared__ float rs[8][5];
    et   = warpSum(et);
    e8   = warpSum(e8);
    e64  = warpSum(e64);
    e512 = warpSum(e512);
    Z    = warpSum(Z);
    if (lid == 0) {
        rs[wid][0] = et; rs[wid][1] = e8; rs[wid][2] = e64;
        rs[wid][3] = e512; rs[wid][4] = Z;
    }
    __syncthreads();

    __shared__ bool isLast;
    if (tid == 0) {
        float s[5] = {0.f, 0.f, 0.f, 0.f, 0.f};
#pragma unroll
        for (int w = 0; w < 8; w++)
#pragma unroll
            for (int k = 0; k < 5; k++) s[k] += rs[w][k];

        float per = 0.f;
#pragma unroll
        for (int j = 0; j < 4; j++) {
            const float numj = s[j], denj = s[j + 1];
            if (numj != 0.f)
                per += weights[t * 4 + j] * (__logf(denj) - __logf(numj));
        }
        g_partial[b] = per;

        // ---- hierarchical ticket: group counter (16-way contention) ... ----
        unsigned int tk1;
        asm volatile("atom.acq_rel.gpu.global.inc.u32 %0, [%1], %2;"
                     : "=r"(tk1)
                     : "l"(&g_cnt[(b & (NGRP - 1)) * CSTRIDE]),
                       "r"((unsigned)(NGRP - 1))
                     : "memory");
        bool last = false;
        if (tk1 == NGRP - 1) {
            // ---- ... then root counter (16 ops total) ----
            unsigned int tk2;
            asm volatile("atom.acq_rel.gpu.global.inc.u32 %0, [%1], %2;"
                         : "=r"(tk2)
                         : "l"(&g_root), "r"((unsigned)(NGRP - 1))
                         : "memory");
            last = (tk2 == NGRP - 1);
        }
        isLast = last;
    }
    __syncthreads();

    // ---- last CTA: deterministic fixed-order batch mean over 256 partials ----
    if (isLast) {
        float x = __ldcg(&g_partial[tid]);   // L2-direct
        x = warpSum(x);
        __shared__ float red[8];
        if (lid == 0) red[wid] = x;
        __syncthreads();
        if (tid < 32) {
            float s = (lid < 8) ? red[lid] : 0.f;
            s = warpSum(s);
            if (lid == 0) out[0] = s * (1.0f / (float)Bn);
        }
    }
}

extern "C" void kernel_launch(void* const* d_in, const int* in_sizes, int n_in,
                              void* d_out, int out_size)
{
    const float* logits  = (const float*)d_in[0];
    const int*   tgt     = (const int*)d_in[1];
    // d_in[2] = onehot_num, d_in[3] = onehot_den  -- structural, unused.
    const float* weights = (const float*)d_in[4];
    float*       out     = (float*)d_out;

    hxe_fused<<<Bn, TPB>>>(logits, tgt, weights, out);
}